// round 15
// baseline (speedup 1.0000x reference)
#include <cuda_runtime.h>
#include <cuda_fp16.h>
#include <cuda_bf16.h>
#include <math.h>
#include <cstdint>

constexpr int BATCH = 4;
constexpr int SEQ   = 4096;
constexpr int CH    = 256;
constexpr int ROWS  = BATCH * SEQ; // 16384

// ---- device scratch ----
__device__ __half g_qh[(size_t)ROWS * CH];
__device__ __half g_kh[(size_t)ROWS * CH];
__device__ __half g_vt[(size_t)BATCH * CH * SEQ];   // V^T per batch: [c][m]
__device__ float  g_o [(size_t)ROWS * CH];
__device__ __half g_Sh[(size_t)BATCH * SEQ * SEQ];  // logits -> probs in place (f16)
__device__ float  g_invZ[ROWS];

// ======================= helpers =======================
__device__ __forceinline__ uint32_t smem_u32(const void* p) {
    uint32_t a;
    asm("{ .reg .u64 t; cvta.to.shared.u64 t, %1; cvt.u32.u64 %0, t; }" : "=r"(a) : "l"(p));
    return a;
}
__device__ __forceinline__ uint32_t pack_h2(float a, float b) {
    __half2 h = __floats2half2_rn(a, b);
    return *(uint32_t*)&h;
}
__device__ __forceinline__ uint32_t pack_bf2(float a, float b) {
    __nv_bfloat162 h = __floats2bfloat162_rn(a, b);
    return *(uint32_t*)&h;
}
__device__ __forceinline__ void ldm_x4(uint32_t (&r)[4], uint32_t addr) {
    asm volatile("ldmatrix.sync.aligned.m8n8.x4.shared.b16 {%0,%1,%2,%3}, [%4];"
        : "=r"(r[0]), "=r"(r[1]), "=r"(r[2]), "=r"(r[3]) : "r"(addr));
}
__device__ __forceinline__ void mma_f16_f32(float (&d)[4], const uint32_t (&a)[4],
                                            uint32_t b0, uint32_t b1) {
    asm volatile("mma.sync.aligned.m16n8k16.row.col.f32.f16.f16.f32 "
        "{%0,%1,%2,%3}, {%4,%5,%6,%7}, {%8,%9}, {%0,%1,%2,%3};"
        : "+f"(d[0]), "+f"(d[1]), "+f"(d[2]), "+f"(d[3])
        : "r"(a[0]), "r"(a[1]), "r"(a[2]), "r"(a[3]), "r"(b0), "r"(b1));
}
__device__ __forceinline__ void mma_f16_f16(uint32_t (&d)[2], const uint32_t (&a)[4],
                                            uint32_t b0, uint32_t b1) {
    asm volatile("mma.sync.aligned.m16n8k16.row.col.f16.f16.f16.f16 "
        "{%0,%1}, {%2,%3,%4,%5}, {%6,%7}, {%0,%1};"
        : "+r"(d[0]), "+r"(d[1])
        : "r"(a[0]), "r"(a[1]), "r"(a[2]), "r"(a[3]), "r"(b0), "r"(b1));
}
__device__ __forceinline__ void mma_bf16(float (&d)[4], const uint32_t (&a)[4],
                                         uint32_t b0, uint32_t b1) {
    asm volatile("mma.sync.aligned.m16n8k16.row.col.f32.bf16.bf16.f32 "
        "{%0,%1,%2,%3}, {%4,%5,%6,%7}, {%8,%9}, {%0,%1,%2,%3};"
        : "+f"(d[0]), "+f"(d[1]), "+f"(d[2]), "+f"(d[3])
        : "r"(a[0]), "r"(a[1]), "r"(a[2]), "r"(a[3]), "r"(b0), "r"(b1));
}

#define CP_ASYNC16(dst, src) asm volatile("cp.async.cg.shared.global [%0], [%1], 16;" :: "r"(dst), "l"(src) : "memory")
#define CP_COMMIT()          asm volatile("cp.async.commit_group;" ::: "memory")
#define CP_WAIT(n)           asm volatile("cp.async.wait_group %0;" :: "n"(n) : "memory")

// ---- 32x64 warp-tile step (f16 data, f32 acc) ----
template <int LDB>
__device__ __forceinline__ void mma_step(uint32_t sa, uint32_t sb, int kb,
                                         int m0b, int n0b, int lane,
                                         float (&acc)[2][8][4])
{
    uint32_t a[2][4];
#pragma unroll
    for (int i = 0; i < 2; ++i)
        ldm_x4(a[i], sa + (uint32_t)(m0b + i * 16 + (lane & 15)) * LDB + kb + ((lane >> 4) << 4));
    uint32_t bb[4][4];
#pragma unroll
    for (int p = 0; p < 4; ++p)
        ldm_x4(bb[p], sb + (uint32_t)(n0b + p * 16 + ((lane >> 4) << 3) + (lane & 7)) * LDB
                      + kb + (((lane >> 3) & 1) << 4));
#pragma unroll
    for (int i = 0; i < 2; ++i)
#pragma unroll
        for (int j = 0; j < 8; ++j)
            mma_f16_f32(acc[i][j], a[i], bb[j >> 1][(j & 1) * 2], bb[j >> 1][(j & 1) * 2 + 1]);
}

// ---- 32x32 warp-tile step (proj) ----
template <int LDB>
__device__ __forceinline__ void mma_step32(uint32_t sa, uint32_t sb, int kb,
                                           int m0b, int n0b, int lane,
                                           float (&acc)[2][4][4])
{
    uint32_t a[2][4];
#pragma unroll
    for (int i = 0; i < 2; ++i)
        ldm_x4(a[i], sa + (uint32_t)(m0b + i * 16 + (lane & 15)) * LDB + kb + ((lane >> 4) << 4));
    uint32_t bb[2][4];
#pragma unroll
    for (int p = 0; p < 2; ++p)
        ldm_x4(bb[p], sb + (uint32_t)(n0b + p * 16 + ((lane >> 4) << 3) + (lane & 7)) * LDB
                      + kb + (((lane >> 3) & 1) << 4));
#pragma unroll
    for (int i = 0; i < 2; ++i)
#pragma unroll
        for (int j = 0; j < 4; ++j)
            mma_f16_f32(acc[i][j], a[i], bb[j >> 1][(j & 1) * 2], bb[j >> 1][(j & 1) * 2 + 1]);
}

// ---- 32x64 warp-tile step, f16 acc (qk) ----
template <int LDB>
__device__ __forceinline__ void mma_step_h(uint32_t sa, uint32_t sb, int kb,
                                           int m0b, int n0b, int lane,
                                           uint32_t (&acc)[2][8][2])
{
    uint32_t a[2][4];
#pragma unroll
    for (int i = 0; i < 2; ++i)
        ldm_x4(a[i], sa + (uint32_t)(m0b + i * 16 + (lane & 15)) * LDB + kb + ((lane >> 4) << 4));
    uint32_t bb[4][4];
#pragma unroll
    for (int p = 0; p < 4; ++p)
        ldm_x4(bb[p], sb + (uint32_t)(n0b + p * 16 + ((lane >> 4) << 3) + (lane & 7)) * LDB
                      + kb + (((lane >> 3) & 1) << 4));
#pragma unroll
    for (int i = 0; i < 2; ++i)
#pragma unroll
        for (int j = 0; j < 8; ++j)
            mma_f16_f16(acc[i][j], a[i], bb[j >> 1][(j & 1) * 2], bb[j >> 1][(j & 1) * 2 + 1]);
}

// strides
constexpr int LD1 = 528;
constexpr int PROJ_AB = 64 * LD1;    // 33792
constexpr int DSP = 192 * LD1;       // 101376
constexpr int LD2 = 144;
constexpr int STG = 128 * LD2;       // 18432
constexpr int DS3 = 6 * STG;         // 110592
constexpr int PV_BSTG  = 256 * LD2;  // 36864
constexpr int PV_STAGE = STG + PV_BSTG;  // 55296
constexpr int DS4 = 4 * PV_STAGE;    // 221184

// ======================= K1: projections — 64x128 tile, 2 CTAs/SM =======================
__global__ __launch_bounds__(256, 2) void proj_mma_kernel(
    const float* __restrict__ q, const float* __restrict__ k, const float* __restrict__ v,
    const float* __restrict__ Wq, const float* __restrict__ bq,
    const float* __restrict__ Wk, const float* __restrict__ bk,
    const float* __restrict__ Wv, const float* __restrict__ bv, int zoff)
{
    extern __shared__ __align__(16) char sm[];
    const uint32_t base = smem_u32(sm);
    const int tid = threadIdx.x, lane = tid & 31, wid = tid >> 5;
    const int row0 = blockIdx.y * 64, col0 = blockIdx.x * 128;
    const int m0b = (wid & 1) * 32, n0b = (wid >> 1) * 32;
    const int zz = blockIdx.z + zoff;

    const float *X, *W, *bias;
    if (zz == 0)      { X = q; W = Wq; bias = bq; }
    else if (zz == 1) { X = k; W = Wk; bias = bk; }
    else              { X = v; W = Wv; bias = bv; }

#pragma unroll
    for (int j = 0; j < 8; ++j) {
        int idx = tid + 256 * j;
        int r = idx >> 5, s = idx & 31;
        const float* xa = X + (size_t)(row0 + r) * CH + s * 8;
        float4 x0 = *(const float4*)xa, x1 = *(const float4*)(xa + 4);
        uint4 av = make_uint4(pack_h2(x0.x, x0.y), pack_h2(x0.z, x0.w),
                              pack_h2(x1.x, x1.y), pack_h2(x1.z, x1.w));
        *(uint4*)(sm + (size_t)r * LD1 + s * 16) = av;
    }
#pragma unroll
    for (int j = 0; j < 16; ++j) {
        int idx = tid + 256 * j;
        int r = idx >> 5, s = idx & 31;
        const float* wa = W + (size_t)(col0 + r) * CH + s * 8;
        float4 w0 = *(const float4*)wa, w1 = *(const float4*)(wa + 4);
        uint4 bv2 = make_uint4(pack_h2(w0.x, w0.y), pack_h2(w0.z, w0.w),
                               pack_h2(w1.x, w1.y), pack_h2(w1.z, w1.w));
        *(uint4*)(sm + PROJ_AB + (size_t)r * LD1 + s * 16) = bv2;
    }
    __syncthreads();

    float acc[2][4][4];
#pragma unroll
    for (int i = 0; i < 2; ++i)
#pragma unroll
        for (int j = 0; j < 4; ++j)
#pragma unroll
            for (int t = 0; t < 4; ++t) acc[i][j][t] = 0.f;

#pragma unroll
    for (int ks = 0; ks < 16; ++ks)
        mma_step32<LD1>(base, base + PROJ_AB, ks * 32, m0b, n0b, lane, acc);

    if (zz < 2) {
        __half* Y = (zz == 0) ? g_qh : g_kh;
#pragma unroll
        for (int i = 0; i < 2; ++i) {
            const int r = row0 + m0b + i * 16 + (lane >> 2);
#pragma unroll
            for (int j = 0; j < 4; ++j) {
                const int c = col0 + n0b + j * 8 + (lane & 3) * 2;
                float2 bv2 = *(const float2*)(bias + c);
                *(uint32_t*)(Y + (size_t)r * CH + c) =
                    pack_h2(acc[i][j][0] + bv2.x, acc[i][j][1] + bv2.y);
                *(uint32_t*)(Y + (size_t)(r + 8) * CH + c) =
                    pack_h2(acc[i][j][2] + bv2.x, acc[i][j][3] + bv2.y);
            }
        }
    } else {
        __syncthreads();
        __half* Cs = (__half*)sm;   // [64][136]
#pragma unroll
        for (int i = 0; i < 2; ++i) {
            const int rl = m0b + i * 16 + (lane >> 2);
#pragma unroll
            for (int j = 0; j < 4; ++j) {
                const int c = n0b + j * 8 + (lane & 3) * 2;
                float2 bv2 = *(const float2*)(bias + col0 + c);
                *(uint32_t*)(Cs + (size_t)rl * 136 + c) =
                    pack_h2(acc[i][j][0] + bv2.x, acc[i][j][1] + bv2.y);
                *(uint32_t*)(Cs + (size_t)(rl + 8) * 136 + c) =
                    pack_h2(acc[i][j][2] + bv2.x, acc[i][j][3] + bv2.y);
            }
        }
        __syncthreads();
        const int b = row0 >> 12;
        const int m0 = row0 & (SEQ - 1);
        __half* dst = g_vt + ((size_t)b * CH + col0) * SEQ + m0;
#pragma unroll
        for (int j = 0; j < 4; ++j) {
            int idx = tid + 256 * j;
            int c = idx >> 3, mu = idx & 7;
            __half tmp[8];
#pragma unroll
            for (int t = 0; t < 8; ++t) tmp[t] = Cs[(size_t)(mu * 8 + t) * 136 + c];
            *(uint4*)(dst + (size_t)c * SEQ + mu * 8) = *(uint4*)tmp;
        }
    }
}

// ======================= K2: S = q k^T per batch (f16 acc, 3-stage) =======================
__global__ __launch_bounds__(256, 2) void qk_mma_kernel(int b)
{
    extern __shared__ __align__(16) char sm[];
    const uint32_t base = smem_u32(sm);
    const int tid = threadIdx.x, lane = tid & 31, wid = tid >> 5;
    const int row0 = blockIdx.y * 128, col0 = blockIdx.x * 128;
    const int m0b = (wid & 3) * 32, n0b = (wid >> 2) * 64;

    const __half* A = g_qh + ((size_t)b * SEQ + row0) * CH;
    const __half* B = g_kh + ((size_t)b * SEQ + col0) * CH;

    uint32_t acc[2][8][2];
#pragma unroll
    for (int i = 0; i < 2; ++i)
#pragma unroll
        for (int j = 0; j < 8; ++j) { acc[i][j][0] = 0u; acc[i][j][1] = 0u; }

    auto issue = [&](int i) {
        const int k0 = i * 64;
        const uint32_t so = (uint32_t)(i % 3) * (2 * STG);
#pragma unroll
        for (int j = 0; j < 4; ++j) {
            int idx = tid + 256 * j;
            int r = idx >> 3, s = idx & 7;
            CP_ASYNC16(base + so + (uint32_t)r * LD2 + s * 16,
                       A + (size_t)r * CH + (k0 + s * 8));
            CP_ASYNC16(base + so + STG + (uint32_t)r * LD2 + s * 16,
                       B + (size_t)r * CH + (k0 + s * 8));
        }
        CP_COMMIT();
    };

    issue(0); issue(1);
    for (int i = 0; i < 4; ++i) {
        if (i + 1 < 4) { CP_WAIT(1); } else { CP_WAIT(0); }
        __syncthreads();
        if (i + 2 < 4) issue(i + 2);
        const uint32_t so = (uint32_t)(i % 3) * (2 * STG);
#pragma unroll
        for (int ks = 0; ks < 4; ++ks)
            mma_step_h<LD2>(base + so, base + so + STG, ks * 32, m0b, n0b, lane, acc);
    }

    __syncthreads();
    __half* Cs = (__half*)sm;
#pragma unroll
    for (int i = 0; i < 2; ++i) {
        const int r = m0b + i * 16 + (lane >> 2);
#pragma unroll
        for (int j = 0; j < 8; ++j) {
            const int c = n0b + j * 8 + (lane & 3) * 2;
            *(uint32_t*)(Cs + (size_t)r * 136 + c)       = acc[i][j][0];
            *(uint32_t*)(Cs + (size_t)(r + 8) * 136 + c) = acc[i][j][1];
        }
    }
    __syncthreads();
    __half* S = g_Sh + (size_t)b * SEQ * SEQ;
#pragma unroll
    for (int j = 0; j < 8; ++j) {
        int idx = tid + 256 * j;
        int r = idx >> 4, s = idx & 15;
        *(uint4*)(S + (size_t)(row0 + r) * SEQ + col0 + s * 8) =
            *(const uint4*)(Cs + (size_t)r * 136 + s * 8);
    }
}

// ======================= K3: stats + exp + Z per row (64 thr, 8x uint4) ===================
__global__ __launch_bounds__(64) void expz_kernel(int rowbase)
{
    const int row = rowbase + blockIdx.x, tid = threadIdx.x;
    const int wid = tid >> 5, lane = tid & 31;
    uint4* srow = (uint4*)(g_Sh + (size_t)row * SEQ);
    uint4 d[8];
#pragma unroll
    for (int t = 0; t < 8; ++t) d[t] = srow[tid + 64 * t];
    float f[64];
#pragma unroll
    for (int t = 0; t < 8; ++t) {
        const uint32_t* u = (const uint32_t*)&d[t];
#pragma unroll
        for (int i = 0; i < 4; ++i) {
            float2 a = __half22float2(*(__half2*)&u[i]);
            f[t * 8 + 2 * i] = a.x; f[t * 8 + 2 * i + 1] = a.y;
        }
    }
    float sum = 0.f, ss = 0.f;
#pragma unroll
    for (int i = 0; i < 64; ++i) { sum += f[i]; ss = fmaf(f[i], f[i], ss); }
#pragma unroll
    for (int o = 16; o > 0; o >>= 1) {
        sum += __shfl_xor_sync(~0u, sum, o);
        ss  += __shfl_xor_sync(~0u, ss, o);
    }
    __shared__ float sA[2], sB[2];
    if (lane == 0) { sA[wid] = sum; sB[wid] = ss; }
    __syncthreads();
    float s  = sA[0] + sA[1];
    float qq = sB[0] + sB[1];
    float mu  = s * (1.f / SEQ);
    float var = qq * (1.f / SEQ) - mu * mu;
    float c   = rsqrtf(var + 1e-5f) * 0.0625f;
    float mc  = mu * c;

    float z = 0.f;
#pragma unroll
    for (int i = 0; i < 64; ++i) {
        float e = __expf(fmaf(f[i], c, -mc));
        f[i] = e; z += e;
    }
#pragma unroll
    for (int o = 16; o > 0; o >>= 1) z += __shfl_xor_sync(~0u, z, o);
    __syncthreads();
    if (lane == 0) sA[wid] = z;
#pragma unroll
    for (int t = 0; t < 8; ++t) {
        uint32_t* u = (uint32_t*)&d[t];
#pragma unroll
        for (int i = 0; i < 4; ++i)
            u[i] = pack_h2(f[t * 8 + 2 * i], f[t * 8 + 2 * i + 1]);
        srow[tid + 64 * t] = d[t];
    }
    __syncthreads();
    if (tid == 0)
        g_invZ[row] = 1.f / (sA[0] + sA[1]);
}

// ======================= K4: O = (P V) * invZ per batch — 512 thr, 4-stage ring ==========
__global__ __launch_bounds__(512, 1) void pv_mma_kernel(int b)
{
    extern __shared__ __align__(16) char sm[];
    const uint32_t base = smem_u32(sm);
    const int tid = threadIdx.x, lane = tid & 31, wid = tid >> 5;
    const int row0 = blockIdx.x * 128;
    const int m0b = (wid & 3) * 32, n0b = (wid >> 2) * 64;

    const __half* P  = g_Sh + (size_t)b * SEQ * SEQ + (size_t)row0 * SEQ;
    const __half* Vt = g_vt + (size_t)b * CH * SEQ;

    float acc[2][8][4];
#pragma unroll
    for (int i = 0; i < 2; ++i)
#pragma unroll
        for (int j = 0; j < 8; ++j)
#pragma unroll
            for (int t = 0; t < 4; ++t) acc[i][j][t] = 0.f;

    auto issue = [&](int i) {
        const int k0 = i * 64;
        const uint32_t so = (uint32_t)(i & 3) * PV_STAGE;
#pragma unroll
        for (int j = 0; j < 2; ++j) {
            int idx = tid + 512 * j;
            int r = idx >> 3, s = idx & 7;
            CP_ASYNC16(base + so + (uint32_t)r * LD2 + s * 16,
                       P + (size_t)r * SEQ + (k0 + s * 8));
        }
#pragma unroll
        for (int j = 0; j < 4; ++j) {
            int idx = tid + 512 * j;
            int r = idx >> 3, s = idx & 7;
            CP_ASYNC16(base + so + STG + (uint32_t)r * LD2 + s * 16,
                       Vt + (size_t)r * SEQ + (k0 + s * 8));
        }
        CP_COMMIT();
    };

    issue(0); issue(1); issue(2); issue(3);
    for (int p = 0; p < 32; ++p) {
        const int i0 = 2 * p;
        if (p > 0) {
            __syncthreads();
            if (i0 + 2 < 64) issue(i0 + 2);
            if (i0 + 3 < 64) issue(i0 + 3);
        }
        if (i0 + 3 < 64) { CP_WAIT(2); } else { CP_WAIT(0); }
        if (p == 0) __syncthreads();
        const uint32_t so0 = (uint32_t)(i0 & 3) * PV_STAGE;
        const uint32_t so1 = (uint32_t)((i0 + 1) & 3) * PV_STAGE;
#pragma unroll
        for (int ks = 0; ks < 4; ++ks)
            mma_step<LD2>(base + so0, base + so0 + STG, ks * 32, m0b, n0b, lane, acc);
#pragma unroll
        for (int ks = 0; ks < 4; ++ks)
            mma_step<LD2>(base + so1, base + so1 + STG, ks * 32, m0b, n0b, lane, acc);
    }

#pragma unroll
    for (int i = 0; i < 2; ++i) {
        const int rl = m0b + i * 16 + (lane >> 2);
        const float izA = g_invZ[b * SEQ + row0 + rl];
        const float izB = g_invZ[b * SEQ + row0 + rl + 8];
#pragma unroll
        for (int j = 0; j < 8; ++j) {
            const int c = n0b + j * 8 + (lane & 3) * 2;
            float2 oA = make_float2(acc[i][j][0] * izA, acc[i][j][1] * izA);
            float2 oB = make_float2(acc[i][j][2] * izB, acc[i][j][3] * izB);
            *(float2*)(g_o + (size_t)(b * SEQ + row0 + rl) * CH + c)     = oA;
            *(float2*)(g_o + (size_t)(b * SEQ + row0 + rl + 8) * CH + c) = oB;
        }
    }
}

// ======================= K5: out = (query + O) @ Wm^T + bm (bf16x3 HMMA, per batch) ======
__global__ __launch_bounds__(256) void final_mma_kernel(
    const float* __restrict__ query, const float* __restrict__ Wm,
    const float* __restrict__ bm, float* __restrict__ out, int rowbase)
{
    extern __shared__ __align__(16) char sm[];
    const uint32_t base = smem_u32(sm);
    const uint32_t sAhi = base, sAlo = base + STG, sBhi = base + 2 * STG, sBlo = base + 3 * STG;
    const int tid = threadIdx.x, lane = tid & 31, wid = tid >> 5;
    const int row0 = rowbase + blockIdx.y * 128, col0 = blockIdx.x * 128;
    const int m0b = (wid & 3) * 32, n0b = (wid >> 2) * 64;

    float acc[2][8][4];
#pragma unroll
    for (int i = 0; i < 2; ++i)
#pragma unroll
        for (int j = 0; j < 8; ++j)
#pragma unroll
            for (int t = 0; t < 4; ++t) acc[i][j][t] = 0.f;

    for (int ch = 0; ch < 4; ++ch) {
        const int k0 = ch * 64;
        __syncthreads();
#pragma unroll
        for (int j = 0; j < 4; ++j) {
            int idx = tid + 256 * j;
            int r = idx >> 3, s = idx & 7;
            const float* qa = query + (size_t)(row0 + r) * CH + k0 + s * 8;
            const float* oa = g_o   + (size_t)(row0 + r) * CH + k0 + s * 8;
            float av[8];
            *(float4*)&av[0] = *(const float4*)qa;
            *(float4*)&av[4] = *(const float4*)(qa + 4);
            float4 o0 = *(const float4*)oa, o1 = *(const float4*)(oa + 4);
            av[0] += o0.x; av[1] += o0.y; av[2] += o0.z; av[3] += o0.w;
            av[4] += o1.x; av[5] += o1.y; av[6] += o1.z; av[7] += o1.w;
            uint4 hi, lo;
            uint32_t* hp = (uint32_t*)&hi; uint32_t* lp = (uint32_t*)&lo;
#pragma unroll
            for (int t = 0; t < 4; ++t) {
                float a0 = av[2 * t], a1 = av[2 * t + 1];
                __nv_bfloat16 h0 = __float2bfloat16_rn(a0), h1 = __float2bfloat16_rn(a1);
                float l0 = a0 - __bfloat162float(h0), l1 = a1 - __bfloat162float(h1);
                hp[t] = ((uint32_t)*(uint16_t*)&h1 << 16) | *(uint16_t*)&h0;
                lp[t] = pack_bf2(l0, l1);
            }
            const uint32_t doff = (uint32_t)r * LD2 + s * 16;
            *(uint4*)(sm + doff)        = hi;
            *(uint4*)(sm + STG + doff)  = lo;

            const float* wa = Wm + (size_t)(col0 + r) * CH + k0 + s * 8;
            float wv[8];
            *(float4*)&wv[0] = *(const float4*)wa;
            *(float4*)&wv[4] = *(const float4*)(wa + 4);
#pragma unroll
            for (int t = 0; t < 4; ++t) {
                float a0 = wv[2 * t], a1 = wv[2 * t + 1];
                __nv_bfloat16 h0 = __float2bfloat16_rn(a0), h1 = __float2bfloat16_rn(a1);
                float l0 = a0 - __bfloat162float(h0), l1 = a1 - __bfloat162float(h1);
                hp[t] = ((uint32_t)*(uint16_t*)&h1 << 16) | *(uint16_t*)&h0;
                lp[t] = pack_bf2(l0, l1);
            }
            *(uint4*)(sm + 2 * STG + doff) = hi;
            *(uint4*)(sm + 3 * STG + doff) = lo;
        }
        __syncthreads();

#pragma unroll
        for (int ks = 0; ks < 4; ++ks) {
            const int kb = ks * 32;
            uint32_t ah[2][4], al[2][4];
#pragma unroll
            for (int i = 0; i < 2; ++i) {
                const uint32_t ao = (uint32_t)(m0b + i * 16 + (lane & 15)) * LD2 + kb + ((lane >> 4) << 4);
                ldm_x4(ah[i], sAhi + ao);
                ldm_x4(al[i], sAlo + ao);
            }
            uint32_t bh[4][4], bl[4][4];
#pragma unroll
            for (int p = 0; p < 4; ++p) {
                const uint32_t bo = (uint32_t)(n0b + p * 16 + ((lane >> 4) << 3) + (lane & 7)) * LD2
                                    + kb + (((lane >> 3) & 1) << 4);
                ldm_x4(bh[p], sBhi + bo);
                ldm_x4(bl[p], sBlo + bo);
            }
#pragma unroll
            for (int i = 0; i < 2; ++i)
#pragma unroll
                for (int j = 0; j < 8; ++j) {
                    uint32_t bh0 = bh[j >> 1][(j & 1) * 2], bh1 = bh[j >> 1][(j & 1) * 2 + 1];
                    uint32_t bl0 = bl[j >> 1][(j & 1) * 2], bl1 = bl[j >> 1][(j & 1) * 2 + 1];
                    mma_bf16(acc[i][j], ah[i], bh0, bh1);
                    mma_bf16(acc[i][j], ah[i], bl0, bl1);
                    mma_bf16(acc[i][j], al[i], bh0, bh1);
                }
        }
    }

#pragma unroll
    for (int i = 0; i < 2; ++i) {
        const int r = row0 + m0b + i * 16 + (lane >> 2);
#pragma unroll
        for (int j = 0; j < 8; ++j) {
            const int c = col0 + n0b + j * 8 + (lane & 3) * 2;
            float2 bv2 = *(const float2*)(bm + c);
            *(float2*)(out + (size_t)r * CH + c) =
                make_float2(acc[i][j][0] + bv2.x, acc[i][j][1] + bv2.y);
            *(float2*)(out + (size_t)(r + 8) * CH + c) =
                make_float2(acc[i][j][2] + bv2.x, acc[i][j][3] + bv2.y);
        }
    }
}

extern "C" void kernel_launch(void* const* d_in, const int* in_sizes, int n_in,
                              void* d_out, int out_size)
{
    const float* query = (const float*)d_in[0];
    const float* key   = (const float*)d_in[1];
    const float* value = (const float*)d_in[2];
    const float* Wq    = (const float*)d_in[3];
    const float* bq    = (const float*)d_in[4];
    const float* Wk    = (const float*)d_in[5];
    const float* bk    = (const float*)d_in[6];
    const float* Wv    = (const float*)d_in[7];
    const float* bv    = (const float*)d_in[8];
    const float* Wm    = (const float*)d_in[9];
    const float* bm    = (const float*)d_in[10];
    float* out = (float*)d_out;

    cudaFuncSetAttribute(proj_mma_kernel,  cudaFuncAttributeMaxDynamicSharedMemorySize, DSP);
    cudaFuncSetAttribute(qk_mma_kernel,    cudaFuncAttributeMaxDynamicSharedMemorySize, DS3);
    cudaFuncSetAttribute(pv_mma_kernel,    cudaFuncAttributeMaxDynamicSharedMemorySize, DS4);
    cudaFuncSetAttribute(final_mma_kernel, cudaFuncAttributeMaxDynamicSharedMemorySize, 4 * STG);

    // Lanes: origin = tensor (proj_qk + qk), stA = memory (proj_V + expz),
    //        stB/stC = per-batch pv+final (interleaved even/odd).
    cudaEvent_t forkEv;
    cudaEventCreateWithFlags(&forkEv, cudaEventDisableTiming);
    cudaEventRecord(forkEv, 0);

    cudaStream_t stA, stB, stC;
    cudaStreamCreateWithFlags(&stA, cudaStreamNonBlocking);
    cudaStreamCreateWithFlags(&stB, cudaStreamNonBlocking);
    cudaStreamCreateWithFlags(&stC, cudaStreamNonBlocking);
    cudaStreamWaitEvent(stA, forkEv, 0);

    cudaEvent_t evQK[BATCH], evEZ[BATCH], evB, evC;

    // origin: proj(q,k), then qk per batch with events
    proj_mma_kernel<<<dim3(2, 256, 2), 256, DSP>>>(query, key, value,
                                                   Wq, bq, Wk, bk, Wv, bv, 0);
    // stA: proj(V)
    proj_mma_kernel<<<dim3(2, 256, 1), 256, DSP, stA>>>(query, key, value,
                                                        Wq, bq, Wk, bk, Wv, bv, 2);

    for (int b = 0; b < BATCH; ++b) {
        qk_mma_kernel<<<dim3(32, 32), 256, DS3>>>(b);
        cudaEventCreateWithFlags(&evQK[b], cudaEventDisableTiming);
        cudaEventRecord(evQK[b], 0);
    }
    for (int b = 0; b < BATCH; ++b) {
        cudaStreamWaitEvent(stA, evQK[b], 0);
        expz_kernel<<<SEQ, 64, 0, stA>>>(b * SEQ);
        cudaEventCreateWithFlags(&evEZ[b], cudaEventDisableTiming);
        cudaEventRecord(evEZ[b], stA);
    }
    // stB: batches 0, 2; stC: batches 1, 3
    for (int b = 0; b < BATCH; ++b) {
        cudaStream_t sp = (b & 1) ? stC : stB;
        cudaStreamWaitEvent(sp, evEZ[b], 0);
        pv_mma_kernel<<<32, 512, DS4, sp>>>(b);
        final_mma_kernel<<<dim3(2, 32), 256, 4 * STG, sp>>>(query, Wm, bm, out, b * SEQ);
    }
    cudaEventCreateWithFlags(&evB, cudaEventDisableTiming);
    cudaEventCreateWithFlags(&evC, cudaEventDisableTiming);
    cudaEventRecord(evB, stB);
    cudaEventRecord(evC, stC);
    cudaStreamWaitEvent(0, evB, 0);
    cudaStreamWaitEvent(0, evC, 0);

    for (int b = 0; b < BATCH; ++b) { cudaEventDestroy(evQK[b]); cudaEventDestroy(evEZ[b]); }
    cudaEventDestroy(evB);
    cudaEventDestroy(evC);
    cudaEventDestroy(forkEv);
    cudaStreamDestroy(stA);
    cudaStreamDestroy(stB);
    cudaStreamDestroy(stC);
}

// round 16
// speedup vs baseline: 1.2485x; 1.2485x over previous
#include <cuda_runtime.h>
#include <cuda_fp16.h>
#include <cuda_bf16.h>
#include <math.h>
#include <cstdint>

constexpr int BATCH = 4;
constexpr int SEQ   = 4096;
constexpr int CH    = 256;
constexpr int ROWS  = BATCH * SEQ; // 16384

// ---- device scratch ----
__device__ __half g_qh[(size_t)ROWS * CH];
__device__ __half g_kh[(size_t)ROWS * CH];
__device__ __half g_vt[(size_t)BATCH * CH * SEQ];   // V^T per batch: [c][m]
__device__ __half g_o [(size_t)ROWS * CH];          // O in f16 (residual-damped)
__device__ __half g_Sh[(size_t)BATCH * SEQ * SEQ];  // logits -> probs in place (f16)
__device__ float  g_invZ[ROWS];

// ======================= helpers =======================
__device__ __forceinline__ uint32_t smem_u32(const void* p) {
    uint32_t a;
    asm("{ .reg .u64 t; cvta.to.shared.u64 t, %1; cvt.u32.u64 %0, t; }" : "=r"(a) : "l"(p));
    return a;
}
__device__ __forceinline__ uint32_t pack_h2(float a, float b) {
    __half2 h = __floats2half2_rn(a, b);
    return *(uint32_t*)&h;
}
__device__ __forceinline__ uint32_t pack_bf2(float a, float b) {
    __nv_bfloat162 h = __floats2bfloat162_rn(a, b);
    return *(uint32_t*)&h;
}
__device__ __forceinline__ void ldm_x4(uint32_t (&r)[4], uint32_t addr) {
    asm volatile("ldmatrix.sync.aligned.m8n8.x4.shared.b16 {%0,%1,%2,%3}, [%4];"
        : "=r"(r[0]), "=r"(r[1]), "=r"(r[2]), "=r"(r[3]) : "r"(addr));
}
__device__ __forceinline__ void mma_f16_f32(float (&d)[4], const uint32_t (&a)[4],
                                            uint32_t b0, uint32_t b1) {
    asm volatile("mma.sync.aligned.m16n8k16.row.col.f32.f16.f16.f32 "
        "{%0,%1,%2,%3}, {%4,%5,%6,%7}, {%8,%9}, {%0,%1,%2,%3};"
        : "+f"(d[0]), "+f"(d[1]), "+f"(d[2]), "+f"(d[3])
        : "r"(a[0]), "r"(a[1]), "r"(a[2]), "r"(a[3]), "r"(b0), "r"(b1));
}
__device__ __forceinline__ void mma_f16_f16(uint32_t (&d)[2], const uint32_t (&a)[4],
                                            uint32_t b0, uint32_t b1) {
    asm volatile("mma.sync.aligned.m16n8k16.row.col.f16.f16.f16.f16 "
        "{%0,%1}, {%2,%3,%4,%5}, {%6,%7}, {%0,%1};"
        : "+r"(d[0]), "+r"(d[1])
        : "r"(a[0]), "r"(a[1]), "r"(a[2]), "r"(a[3]), "r"(b0), "r"(b1));
}
__device__ __forceinline__ void mma_bf16(float (&d)[4], const uint32_t (&a)[4],
                                         uint32_t b0, uint32_t b1) {
    asm volatile("mma.sync.aligned.m16n8k16.row.col.f32.bf16.bf16.f32 "
        "{%0,%1,%2,%3}, {%4,%5,%6,%7}, {%8,%9}, {%0,%1,%2,%3};"
        : "+f"(d[0]), "+f"(d[1]), "+f"(d[2]), "+f"(d[3])
        : "r"(a[0]), "r"(a[1]), "r"(a[2]), "r"(a[3]), "r"(b0), "r"(b1));
}

#define CP_ASYNC16(dst, src) asm volatile("cp.async.cg.shared.global [%0], [%1], 16;" :: "r"(dst), "l"(src) : "memory")
#define CP_COMMIT()          asm volatile("cp.async.commit_group;" ::: "memory")
#define CP_WAIT(n)           asm volatile("cp.async.wait_group %0;" :: "n"(n) : "memory")

// ---- 32x64 warp-tile step (f16 data, f32 acc) ----
template <int LDB>
__device__ __forceinline__ void mma_step(uint32_t sa, uint32_t sb, int kb,
                                         int m0b, int n0b, int lane,
                                         float (&acc)[2][8][4])
{
    uint32_t a[2][4];
#pragma unroll
    for (int i = 0; i < 2; ++i)
        ldm_x4(a[i], sa + (uint32_t)(m0b + i * 16 + (lane & 15)) * LDB + kb + ((lane >> 4) << 4));
    uint32_t bb[4][4];
#pragma unroll
    for (int p = 0; p < 4; ++p)
        ldm_x4(bb[p], sb + (uint32_t)(n0b + p * 16 + ((lane >> 4) << 3) + (lane & 7)) * LDB
                      + kb + (((lane >> 3) & 1) << 4));
#pragma unroll
    for (int i = 0; i < 2; ++i)
#pragma unroll
        for (int j = 0; j < 8; ++j)
            mma_f16_f32(acc[i][j], a[i], bb[j >> 1][(j & 1) * 2], bb[j >> 1][(j & 1) * 2 + 1]);
}

// ---- 32x32 warp-tile step (proj) ----
template <int LDB>
__device__ __forceinline__ void mma_step32(uint32_t sa, uint32_t sb, int kb,
                                           int m0b, int n0b, int lane,
                                           float (&acc)[2][4][4])
{
    uint32_t a[2][4];
#pragma unroll
    for (int i = 0; i < 2; ++i)
        ldm_x4(a[i], sa + (uint32_t)(m0b + i * 16 + (lane & 15)) * LDB + kb + ((lane >> 4) << 4));
    uint32_t bb[2][4];
#pragma unroll
    for (int p = 0; p < 2; ++p)
        ldm_x4(bb[p], sb + (uint32_t)(n0b + p * 16 + ((lane >> 4) << 3) + (lane & 7)) * LDB
                      + kb + (((lane >> 3) & 1) << 4));
#pragma unroll
    for (int i = 0; i < 2; ++i)
#pragma unroll
        for (int j = 0; j < 4; ++j)
            mma_f16_f32(acc[i][j], a[i], bb[j >> 1][(j & 1) * 2], bb[j >> 1][(j & 1) * 2 + 1]);
}

// ---- 32x64 warp-tile step, f16 acc (qk) ----
template <int LDB>
__device__ __forceinline__ void mma_step_h(uint32_t sa, uint32_t sb, int kb,
                                           int m0b, int n0b, int lane,
                                           uint32_t (&acc)[2][8][2])
{
    uint32_t a[2][4];
#pragma unroll
    for (int i = 0; i < 2; ++i)
        ldm_x4(a[i], sa + (uint32_t)(m0b + i * 16 + (lane & 15)) * LDB + kb + ((lane >> 4) << 4));
    uint32_t bb[4][4];
#pragma unroll
    for (int p = 0; p < 4; ++p)
        ldm_x4(bb[p], sb + (uint32_t)(n0b + p * 16 + ((lane >> 4) << 3) + (lane & 7)) * LDB
                      + kb + (((lane >> 3) & 1) << 4));
#pragma unroll
    for (int i = 0; i < 2; ++i)
#pragma unroll
        for (int j = 0; j < 8; ++j)
            mma_f16_f16(acc[i][j], a[i], bb[j >> 1][(j & 1) * 2], bb[j >> 1][(j & 1) * 2 + 1]);
}

// strides
constexpr int LD1 = 528;
constexpr int PROJ_AB = 64 * LD1;    // 33792
constexpr int DSP = 192 * LD1;       // 101376
constexpr int LD2 = 144;
constexpr int STG = 128 * LD2;       // 18432
constexpr int DS3 = 6 * STG;         // 110592
constexpr int PV_BSTG  = 256 * LD2;  // 36864
constexpr int PV_STAGE = STG + PV_BSTG;  // 55296
constexpr int DS4 = 4 * PV_STAGE;    // 221184

// ======================= K1: projections — 64x128 tile, 2 CTAs/SM =======================
__global__ __launch_bounds__(256, 2) void proj_mma_kernel(
    const float* __restrict__ q, const float* __restrict__ k, const float* __restrict__ v,
    const float* __restrict__ Wq, const float* __restrict__ bq,
    const float* __restrict__ Wk, const float* __restrict__ bk,
    const float* __restrict__ Wv, const float* __restrict__ bv)
{
    extern __shared__ __align__(16) char sm[];
    const uint32_t base = smem_u32(sm);
    const int tid = threadIdx.x, lane = tid & 31, wid = tid >> 5;
    const int row0 = blockIdx.y * 64, col0 = blockIdx.x * 128;
    const int m0b = (wid & 1) * 32, n0b = (wid >> 1) * 32;
    const int zz = blockIdx.z;

    const float *X, *W, *bias;
    if (zz == 0)      { X = q; W = Wq; bias = bq; }
    else if (zz == 1) { X = k; W = Wk; bias = bk; }
    else              { X = v; W = Wv; bias = bv; }

#pragma unroll
    for (int j = 0; j < 8; ++j) {
        int idx = tid + 256 * j;
        int r = idx >> 5, s = idx & 31;
        const float* xa = X + (size_t)(row0 + r) * CH + s * 8;
        float4 x0 = *(const float4*)xa, x1 = *(const float4*)(xa + 4);
        uint4 av = make_uint4(pack_h2(x0.x, x0.y), pack_h2(x0.z, x0.w),
                              pack_h2(x1.x, x1.y), pack_h2(x1.z, x1.w));
        *(uint4*)(sm + (size_t)r * LD1 + s * 16) = av;
    }
#pragma unroll
    for (int j = 0; j < 16; ++j) {
        int idx = tid + 256 * j;
        int r = idx >> 5, s = idx & 31;
        const float* wa = W + (size_t)(col0 + r) * CH + s * 8;
        float4 w0 = *(const float4*)wa, w1 = *(const float4*)(wa + 4);
        uint4 bv2 = make_uint4(pack_h2(w0.x, w0.y), pack_h2(w0.z, w0.w),
                               pack_h2(w1.x, w1.y), pack_h2(w1.z, w1.w));
        *(uint4*)(sm + PROJ_AB + (size_t)r * LD1 + s * 16) = bv2;
    }
    __syncthreads();

    float acc[2][4][4];
#pragma unroll
    for (int i = 0; i < 2; ++i)
#pragma unroll
        for (int j = 0; j < 4; ++j)
#pragma unroll
            for (int t = 0; t < 4; ++t) acc[i][j][t] = 0.f;

#pragma unroll
    for (int ks = 0; ks < 16; ++ks)
        mma_step32<LD1>(base, base + PROJ_AB, ks * 32, m0b, n0b, lane, acc);

    if (zz < 2) {
        __half* Y = (zz == 0) ? g_qh : g_kh;
#pragma unroll
        for (int i = 0; i < 2; ++i) {
            const int r = row0 + m0b + i * 16 + (lane >> 2);
#pragma unroll
            for (int j = 0; j < 4; ++j) {
                const int c = col0 + n0b + j * 8 + (lane & 3) * 2;
                float2 bv2 = *(const float2*)(bias + c);
                *(uint32_t*)(Y + (size_t)r * CH + c) =
                    pack_h2(acc[i][j][0] + bv2.x, acc[i][j][1] + bv2.y);
                *(uint32_t*)(Y + (size_t)(r + 8) * CH + c) =
                    pack_h2(acc[i][j][2] + bv2.x, acc[i][j][3] + bv2.y);
            }
        }
    } else {
        __syncthreads();
        __half* Cs = (__half*)sm;   // [64][136]
#pragma unroll
        for (int i = 0; i < 2; ++i) {
            const int rl = m0b + i * 16 + (lane >> 2);
#pragma unroll
            for (int j = 0; j < 4; ++j) {
                const int c = n0b + j * 8 + (lane & 3) * 2;
                float2 bv2 = *(const float2*)(bias + col0 + c);
                *(uint32_t*)(Cs + (size_t)rl * 136 + c) =
                    pack_h2(acc[i][j][0] + bv2.x, acc[i][j][1] + bv2.y);
                *(uint32_t*)(Cs + (size_t)(rl + 8) * 136 + c) =
                    pack_h2(acc[i][j][2] + bv2.x, acc[i][j][3] + bv2.y);
            }
        }
        __syncthreads();
        const int b = row0 >> 12;
        const int m0 = row0 & (SEQ - 1);
        __half* dst = g_vt + ((size_t)b * CH + col0) * SEQ + m0;
#pragma unroll
        for (int j = 0; j < 4; ++j) {
            int idx = tid + 256 * j;
            int c = idx >> 3, mu = idx & 7;
            __half tmp[8];
#pragma unroll
            for (int t = 0; t < 8; ++t) tmp[t] = Cs[(size_t)(mu * 8 + t) * 136 + c];
            *(uint4*)(dst + (size_t)c * SEQ + mu * 8) = *(uint4*)tmp;
        }
    }
}

// ======================= K2: S = q k^T per batch (f16 acc, 3-stage) =======================
__global__ __launch_bounds__(256, 2) void qk_mma_kernel(int b)
{
    extern __shared__ __align__(16) char sm[];
    const uint32_t base = smem_u32(sm);
    const int tid = threadIdx.x, lane = tid & 31, wid = tid >> 5;
    const int row0 = blockIdx.y * 128, col0 = blockIdx.x * 128;
    const int m0b = (wid & 3) * 32, n0b = (wid >> 2) * 64;

    const __half* A = g_qh + ((size_t)b * SEQ + row0) * CH;
    const __half* B = g_kh + ((size_t)b * SEQ + col0) * CH;

    uint32_t acc[2][8][2];
#pragma unroll
    for (int i = 0; i < 2; ++i)
#pragma unroll
        for (int j = 0; j < 8; ++j) { acc[i][j][0] = 0u; acc[i][j][1] = 0u; }

    auto issue = [&](int i) {
        const int k0 = i * 64;
        const uint32_t so = (uint32_t)(i % 3) * (2 * STG);
#pragma unroll
        for (int j = 0; j < 4; ++j) {
            int idx = tid + 256 * j;
            int r = idx >> 3, s = idx & 7;
            CP_ASYNC16(base + so + (uint32_t)r * LD2 + s * 16,
                       A + (size_t)r * CH + (k0 + s * 8));
            CP_ASYNC16(base + so + STG + (uint32_t)r * LD2 + s * 16,
                       B + (size_t)r * CH + (k0 + s * 8));
        }
        CP_COMMIT();
    };

    issue(0); issue(1);
    for (int i = 0; i < 4; ++i) {
        if (i + 1 < 4) { CP_WAIT(1); } else { CP_WAIT(0); }
        __syncthreads();
        if (i + 2 < 4) issue(i + 2);
        const uint32_t so = (uint32_t)(i % 3) * (2 * STG);
#pragma unroll
        for (int ks = 0; ks < 4; ++ks)
            mma_step_h<LD2>(base + so, base + so + STG, ks * 32, m0b, n0b, lane, acc);
    }

    __syncthreads();
    __half* Cs = (__half*)sm;
#pragma unroll
    for (int i = 0; i < 2; ++i) {
        const int r = m0b + i * 16 + (lane >> 2);
#pragma unroll
        for (int j = 0; j < 8; ++j) {
            const int c = n0b + j * 8 + (lane & 3) * 2;
            *(uint32_t*)(Cs + (size_t)r * 136 + c)       = acc[i][j][0];
            *(uint32_t*)(Cs + (size_t)(r + 8) * 136 + c) = acc[i][j][1];
        }
    }
    __syncthreads();
    __half* S = g_Sh + (size_t)b * SEQ * SEQ;
#pragma unroll
    for (int j = 0; j < 8; ++j) {
        int idx = tid + 256 * j;
        int r = idx >> 4, s = idx & 15;
        *(uint4*)(S + (size_t)(row0 + r) * SEQ + col0 + s * 8) =
            *(const uint4*)(Cs + (size_t)r * 136 + s * 8);
    }
}

// ======================= K3: stats + exp + Z per row (64 thr, 8x uint4) ===================
__global__ __launch_bounds__(64) void expz_kernel(int rowbase)
{
    const int row = rowbase + blockIdx.x, tid = threadIdx.x;
    const int wid = tid >> 5, lane = tid & 31;
    uint4* srow = (uint4*)(g_Sh + (size_t)row * SEQ);
    uint4 d[8];
#pragma unroll
    for (int t = 0; t < 8; ++t) d[t] = srow[tid + 64 * t];
    float f[64];
#pragma unroll
    for (int t = 0; t < 8; ++t) {
        const uint32_t* u = (const uint32_t*)&d[t];
#pragma unroll
        for (int i = 0; i < 4; ++i) {
            float2 a = __half22float2(*(__half2*)&u[i]);
            f[t * 8 + 2 * i] = a.x; f[t * 8 + 2 * i + 1] = a.y;
        }
    }
    float sum = 0.f, ss = 0.f;
#pragma unroll
    for (int i = 0; i < 64; ++i) { sum += f[i]; ss = fmaf(f[i], f[i], ss); }
#pragma unroll
    for (int o = 16; o > 0; o >>= 1) {
        sum += __shfl_xor_sync(~0u, sum, o);
        ss  += __shfl_xor_sync(~0u, ss, o);
    }
    __shared__ float sA[2], sB[2];
    if (lane == 0) { sA[wid] = sum; sB[wid] = ss; }
    __syncthreads();
    float s  = sA[0] + sA[1];
    float qq = sB[0] + sB[1];
    float mu  = s * (1.f / SEQ);
    float var = qq * (1.f / SEQ) - mu * mu;
    float c   = rsqrtf(var + 1e-5f) * 0.0625f;
    float mc  = mu * c;

    float z = 0.f;
#pragma unroll
    for (int i = 0; i < 64; ++i) {
        float e = __expf(fmaf(f[i], c, -mc));
        f[i] = e; z += e;
    }
#pragma unroll
    for (int o = 16; o > 0; o >>= 1) z += __shfl_xor_sync(~0u, z, o);
    __syncthreads();
    if (lane == 0) sA[wid] = z;
#pragma unroll
    for (int t = 0; t < 8; ++t) {
        uint32_t* u = (uint32_t*)&d[t];
#pragma unroll
        for (int i = 0; i < 4; ++i)
            u[i] = pack_h2(f[t * 8 + 2 * i], f[t * 8 + 2 * i + 1]);
        srow[tid + 64 * t] = d[t];
    }
    __syncthreads();
    if (tid == 0)
        g_invZ[row] = 1.f / (sA[0] + sA[1]);
}

// ======================= K4: O = (P V) * invZ per batch — 512 thr, 4-stage ring ==========
__global__ __launch_bounds__(512, 1) void pv_mma_kernel(int b)
{
    extern __shared__ __align__(16) char sm[];
    const uint32_t base = smem_u32(sm);
    const int tid = threadIdx.x, lane = tid & 31, wid = tid >> 5;
    const int row0 = blockIdx.x * 128;
    const int m0b = (wid & 3) * 32, n0b = (wid >> 2) * 64;

    const __half* P  = g_Sh + (size_t)b * SEQ * SEQ + (size_t)row0 * SEQ;
    const __half* Vt = g_vt + (size_t)b * CH * SEQ;

    float acc[2][8][4];
#pragma unroll
    for (int i = 0; i < 2; ++i)
#pragma unroll
        for (int j = 0; j < 8; ++j)
#pragma unroll
            for (int t = 0; t < 4; ++t) acc[i][j][t] = 0.f;

    auto issue = [&](int i) {
        const int k0 = i * 64;
        const uint32_t so = (uint32_t)(i & 3) * PV_STAGE;
#pragma unroll
        for (int j = 0; j < 2; ++j) {
            int idx = tid + 512 * j;
            int r = idx >> 3, s = idx & 7;
            CP_ASYNC16(base + so + (uint32_t)r * LD2 + s * 16,
                       P + (size_t)r * SEQ + (k0 + s * 8));
        }
#pragma unroll
        for (int j = 0; j < 4; ++j) {
            int idx = tid + 512 * j;
            int r = idx >> 3, s = idx & 7;
            CP_ASYNC16(base + so + STG + (uint32_t)r * LD2 + s * 16,
                       Vt + (size_t)r * SEQ + (k0 + s * 8));
        }
        CP_COMMIT();
    };

    issue(0); issue(1); issue(2); issue(3);
    for (int p = 0; p < 32; ++p) {
        const int i0 = 2 * p;
        if (p > 0) {
            __syncthreads();
            if (i0 + 2 < 64) issue(i0 + 2);
            if (i0 + 3 < 64) issue(i0 + 3);
        }
        if (i0 + 3 < 64) { CP_WAIT(2); } else { CP_WAIT(0); }
        if (p == 0) __syncthreads();
        const uint32_t so0 = (uint32_t)(i0 & 3) * PV_STAGE;
        const uint32_t so1 = (uint32_t)((i0 + 1) & 3) * PV_STAGE;
#pragma unroll
        for (int ks = 0; ks < 4; ++ks)
            mma_step<LD2>(base + so0, base + so0 + STG, ks * 32, m0b, n0b, lane, acc);
#pragma unroll
        for (int ks = 0; ks < 4; ++ks)
            mma_step<LD2>(base + so1, base + so1 + STG, ks * 32, m0b, n0b, lane, acc);
    }

#pragma unroll
    for (int i = 0; i < 2; ++i) {
        const int rl = m0b + i * 16 + (lane >> 2);
        const float izA = g_invZ[b * SEQ + row0 + rl];
        const float izB = g_invZ[b * SEQ + row0 + rl + 8];
#pragma unroll
        for (int j = 0; j < 8; ++j) {
            const int c = n0b + j * 8 + (lane & 3) * 2;
            *(uint32_t*)(g_o + (size_t)(b * SEQ + row0 + rl) * CH + c) =
                pack_h2(acc[i][j][0] * izA, acc[i][j][1] * izA);
            *(uint32_t*)(g_o + (size_t)(b * SEQ + row0 + rl + 8) * CH + c) =
                pack_h2(acc[i][j][2] * izB, acc[i][j][3] * izB);
        }
    }
}

// ======================= K5: out = (query + O) @ Wm^T + bm (bf16x3 HMMA, per batch) ======
__global__ __launch_bounds__(256) void final_mma_kernel(
    const float* __restrict__ query, const float* __restrict__ Wm,
    const float* __restrict__ bm, float* __restrict__ out, int rowbase)
{
    extern __shared__ __align__(16) char sm[];
    const uint32_t base = smem_u32(sm);
    const uint32_t sAhi = base, sAlo = base + STG, sBhi = base + 2 * STG, sBlo = base + 3 * STG;
    const int tid = threadIdx.x, lane = tid & 31, wid = tid >> 5;
    const int row0 = rowbase + blockIdx.y * 128, col0 = blockIdx.x * 128;
    const int m0b = (wid & 3) * 32, n0b = (wid >> 2) * 64;

    float acc[2][8][4];
#pragma unroll
    for (int i = 0; i < 2; ++i)
#pragma unroll
        for (int j = 0; j < 8; ++j)
#pragma unroll
            for (int t = 0; t < 4; ++t) acc[i][j][t] = 0.f;

    for (int ch = 0; ch < 4; ++ch) {
        const int k0 = ch * 64;
        __syncthreads();
#pragma unroll
        for (int j = 0; j < 4; ++j) {
            int idx = tid + 256 * j;
            int r = idx >> 3, s = idx & 7;
            const float* qa = query + (size_t)(row0 + r) * CH + k0 + s * 8;
            const __half* oa = g_o  + (size_t)(row0 + r) * CH + k0 + s * 8;
            float av[8];
            *(float4*)&av[0] = *(const float4*)qa;
            *(float4*)&av[4] = *(const float4*)(qa + 4);
            uint4 ov = *(const uint4*)oa;
            const uint32_t* ou = (const uint32_t*)&ov;
#pragma unroll
            for (int t = 0; t < 4; ++t) {
                float2 o2 = __half22float2(*(__half2*)&ou[t]);
                av[2 * t]     += o2.x;
                av[2 * t + 1] += o2.y;
            }
            uint4 hi, lo;
            uint32_t* hp = (uint32_t*)&hi; uint32_t* lp = (uint32_t*)&lo;
#pragma unroll
            for (int t = 0; t < 4; ++t) {
                float a0 = av[2 * t], a1 = av[2 * t + 1];
                __nv_bfloat16 h0 = __float2bfloat16_rn(a0), h1 = __float2bfloat16_rn(a1);
                float l0 = a0 - __bfloat162float(h0), l1 = a1 - __bfloat162float(h1);
                hp[t] = ((uint32_t)*(uint16_t*)&h1 << 16) | *(uint16_t*)&h0;
                lp[t] = pack_bf2(l0, l1);
            }
            const uint32_t doff = (uint32_t)r * LD2 + s * 16;
            *(uint4*)(sm + doff)        = hi;
            *(uint4*)(sm + STG + doff)  = lo;

            const float* wa = Wm + (size_t)(col0 + r) * CH + k0 + s * 8;
            float wv[8];
            *(float4*)&wv[0] = *(const float4*)wa;
            *(float4*)&wv[4] = *(const float4*)(wa + 4);
#pragma unroll
            for (int t = 0; t < 4; ++t) {
                float a0 = wv[2 * t], a1 = wv[2 * t + 1];
                __nv_bfloat16 h0 = __float2bfloat16_rn(a0), h1 = __float2bfloat16_rn(a1);
                float l0 = a0 - __bfloat162float(h0), l1 = a1 - __bfloat162float(h1);
                hp[t] = ((uint32_t)*(uint16_t*)&h1 << 16) | *(uint16_t*)&h0;
                lp[t] = pack_bf2(l0, l1);
            }
            *(uint4*)(sm + 2 * STG + doff) = hi;
            *(uint4*)(sm + 3 * STG + doff) = lo;
        }
        __syncthreads();

#pragma unroll
        for (int ks = 0; ks < 4; ++ks) {
            const int kb = ks * 32;
            uint32_t ah[2][4], al[2][4];
#pragma unroll
            for (int i = 0; i < 2; ++i) {
                const uint32_t ao = (uint32_t)(m0b + i * 16 + (lane & 15)) * LD2 + kb + ((lane >> 4) << 4);
                ldm_x4(ah[i], sAhi + ao);
                ldm_x4(al[i], sAlo + ao);
            }
            uint32_t bh[4][4], bl[4][4];
#pragma unroll
            for (int p = 0; p < 4; ++p) {
                const uint32_t bo = (uint32_t)(n0b + p * 16 + ((lane >> 4) << 3) + (lane & 7)) * LD2
                                    + kb + (((lane >> 3) & 1) << 4);
                ldm_x4(bh[p], sBhi + bo);
                ldm_x4(bl[p], sBlo + bo);
            }
#pragma unroll
            for (int i = 0; i < 2; ++i)
#pragma unroll
                for (int j = 0; j < 8; ++j) {
                    uint32_t bh0 = bh[j >> 1][(j & 1) * 2], bh1 = bh[j >> 1][(j & 1) * 2 + 1];
                    uint32_t bl0 = bl[j >> 1][(j & 1) * 2], bl1 = bl[j >> 1][(j & 1) * 2 + 1];
                    mma_bf16(acc[i][j], ah[i], bh0, bh1);
                    mma_bf16(acc[i][j], ah[i], bl0, bl1);
                    mma_bf16(acc[i][j], al[i], bh0, bh1);
                }
        }
    }

#pragma unroll
    for (int i = 0; i < 2; ++i) {
        const int r = row0 + m0b + i * 16 + (lane >> 2);
#pragma unroll
        for (int j = 0; j < 8; ++j) {
            const int c = col0 + n0b + j * 8 + (lane & 3) * 2;
            float2 bv2 = *(const float2*)(bm + c);
            *(float2*)(out + (size_t)r * CH + c) =
                make_float2(acc[i][j][0] + bv2.x, acc[i][j][1] + bv2.y);
            *(float2*)(out + (size_t)(r + 8) * CH + c) =
                make_float2(acc[i][j][2] + bv2.x, acc[i][j][3] + bv2.y);
        }
    }
}

extern "C" void kernel_launch(void* const* d_in, const int* in_sizes, int n_in,
                              void* d_out, int out_size)
{
    const float* query = (const float*)d_in[0];
    const float* key   = (const float*)d_in[1];
    const float* value = (const float*)d_in[2];
    const float* Wq    = (const float*)d_in[3];
    const float* bq    = (const float*)d_in[4];
    const float* Wk    = (const float*)d_in[5];
    const float* bk    = (const float*)d_in[6];
    const float* Wv    = (const float*)d_in[7];
    const float* bv    = (const float*)d_in[8];
    const float* Wm    = (const float*)d_in[9];
    const float* bm    = (const float*)d_in[10];
    float* out = (float*)d_out;

    cudaFuncSetAttribute(proj_mma_kernel,  cudaFuncAttributeMaxDynamicSharedMemorySize, DSP);
    cudaFuncSetAttribute(qk_mma_kernel,    cudaFuncAttributeMaxDynamicSharedMemorySize, DS3);
    cudaFuncSetAttribute(pv_mma_kernel,    cudaFuncAttributeMaxDynamicSharedMemorySize, DS4);
    cudaFuncSetAttribute(final_mma_kernel, cudaFuncAttributeMaxDynamicSharedMemorySize, 4 * STG);

    // ---- projections on the origin (capture) stream ----
    proj_mma_kernel<<<dim3(2, 256, 3), 256, DSP>>>(query, key, value, Wq, bq, Wk, bk, Wv, bv);

    // ---- fork 4 per-batch chains: qk(b) -> expz(b) -> pv(b) -> final(b) ----
    cudaEvent_t forkEv;
    cudaEventCreateWithFlags(&forkEv, cudaEventDisableTiming);
    cudaEventRecord(forkEv, 0);

    cudaStream_t st[BATCH];
    cudaEvent_t  joinEv[BATCH];
    for (int b = 0; b < BATCH; ++b) {
        cudaStreamCreateWithFlags(&st[b], cudaStreamNonBlocking);
        cudaStreamWaitEvent(st[b], forkEv, 0);
        qk_mma_kernel<<<dim3(32, 32), 256, DS3, st[b]>>>(b);
        expz_kernel<<<SEQ, 64, 0, st[b]>>>(b * SEQ);
        pv_mma_kernel<<<32, 512, DS4, st[b]>>>(b);
        final_mma_kernel<<<dim3(2, 32), 256, 4 * STG, st[b]>>>(query, Wm, bm, out, b * SEQ);
        cudaEventCreateWithFlags(&joinEv[b], cudaEventDisableTiming);
        cudaEventRecord(joinEv[b], st[b]);
        cudaStreamWaitEvent(0, joinEv[b], 0);
    }

    for (int b = 0; b < BATCH; ++b) {
        cudaStreamDestroy(st[b]);
        cudaEventDestroy(joinEv[b]);
    }
    cudaEventDestroy(forkEv);
}

// round 17
// speedup vs baseline: 1.3131x; 1.0518x over previous
#include <cuda_runtime.h>
#include <cuda_fp16.h>
#include <cuda_bf16.h>
#include <math.h>
#include <cstdint>

constexpr int BATCH = 4;
constexpr int SEQ   = 4096;
constexpr int CH    = 256;
constexpr int ROWS  = BATCH * SEQ; // 16384

// ---- device scratch ----
__device__ __half g_qh[(size_t)ROWS * CH];
__device__ __half g_kh[(size_t)ROWS * CH];
__device__ __half g_vt[(size_t)BATCH * CH * SEQ];   // V^T per batch: [c][m]
__device__ __half g_Sh[(size_t)BATCH * SEQ * SEQ];  // logits -> probs in place (f16)
__device__ float  g_invZ[ROWS];

// ======================= helpers =======================
__device__ __forceinline__ uint32_t smem_u32(const void* p) {
    uint32_t a;
    asm("{ .reg .u64 t; cvta.to.shared.u64 t, %1; cvt.u32.u64 %0, t; }" : "=r"(a) : "l"(p));
    return a;
}
__device__ __forceinline__ uint32_t pack_h2(float a, float b) {
    __half2 h = __floats2half2_rn(a, b);
    return *(uint32_t*)&h;
}
__device__ __forceinline__ uint32_t pack_bf2(float a, float b) {
    __nv_bfloat162 h = __floats2bfloat162_rn(a, b);
    return *(uint32_t*)&h;
}
__device__ __forceinline__ void ldm_x4(uint32_t (&r)[4], uint32_t addr) {
    asm volatile("ldmatrix.sync.aligned.m8n8.x4.shared.b16 {%0,%1,%2,%3}, [%4];"
        : "=r"(r[0]), "=r"(r[1]), "=r"(r[2]), "=r"(r[3]) : "r"(addr));
}
__device__ __forceinline__ void mma_f16_f32(float (&d)[4], const uint32_t (&a)[4],
                                            uint32_t b0, uint32_t b1) {
    asm volatile("mma.sync.aligned.m16n8k16.row.col.f32.f16.f16.f32 "
        "{%0,%1,%2,%3}, {%4,%5,%6,%7}, {%8,%9}, {%0,%1,%2,%3};"
        : "+f"(d[0]), "+f"(d[1]), "+f"(d[2]), "+f"(d[3])
        : "r"(a[0]), "r"(a[1]), "r"(a[2]), "r"(a[3]), "r"(b0), "r"(b1));
}
__device__ __forceinline__ void mma_f16_f16(uint32_t (&d)[2], const uint32_t (&a)[4],
                                            uint32_t b0, uint32_t b1) {
    asm volatile("mma.sync.aligned.m16n8k16.row.col.f16.f16.f16.f16 "
        "{%0,%1}, {%2,%3,%4,%5}, {%6,%7}, {%0,%1};"
        : "+r"(d[0]), "+r"(d[1])
        : "r"(a[0]), "r"(a[1]), "r"(a[2]), "r"(a[3]), "r"(b0), "r"(b1));
}
__device__ __forceinline__ void mma_bf16(float (&d)[4], const uint32_t (&a)[4],
                                         uint32_t b0, uint32_t b1) {
    asm volatile("mma.sync.aligned.m16n8k16.row.col.f32.bf16.bf16.f32 "
        "{%0,%1,%2,%3}, {%4,%5,%6,%7}, {%8,%9}, {%0,%1,%2,%3};"
        : "+f"(d[0]), "+f"(d[1]), "+f"(d[2]), "+f"(d[3])
        : "r"(a[0]), "r"(a[1]), "r"(a[2]), "r"(a[3]), "r"(b0), "r"(b1));
}

#define CP_ASYNC16(dst, src) asm volatile("cp.async.cg.shared.global [%0], [%1], 16;" :: "r"(dst), "l"(src) : "memory")
#define CP_COMMIT()          asm volatile("cp.async.commit_group;" ::: "memory")
#define CP_WAIT(n)           asm volatile("cp.async.wait_group %0;" :: "n"(n) : "memory")

// ---- 32x64 warp-tile step (f16 data, f32 acc) ----
template <int LDB>
__device__ __forceinline__ void mma_step(uint32_t sa, uint32_t sb, int kb,
                                         int m0b, int n0b, int lane,
                                         float (&acc)[2][8][4])
{
    uint32_t a[2][4];
#pragma unroll
    for (int i = 0; i < 2; ++i)
        ldm_x4(a[i], sa + (uint32_t)(m0b + i * 16 + (lane & 15)) * LDB + kb + ((lane >> 4) << 4));
    uint32_t bb[4][4];
#pragma unroll
    for (int p = 0; p < 4; ++p)
        ldm_x4(bb[p], sb + (uint32_t)(n0b + p * 16 + ((lane >> 4) << 3) + (lane & 7)) * LDB
                      + kb + (((lane >> 3) & 1) << 4));
#pragma unroll
    for (int i = 0; i < 2; ++i)
#pragma unroll
        for (int j = 0; j < 8; ++j)
            mma_f16_f32(acc[i][j], a[i], bb[j >> 1][(j & 1) * 2], bb[j >> 1][(j & 1) * 2 + 1]);
}

// ---- 32x32 warp-tile step (proj) ----
template <int LDB>
__device__ __forceinline__ void mma_step32(uint32_t sa, uint32_t sb, int kb,
                                           int m0b, int n0b, int lane,
                                           float (&acc)[2][4][4])
{
    uint32_t a[2][4];
#pragma unroll
    for (int i = 0; i < 2; ++i)
        ldm_x4(a[i], sa + (uint32_t)(m0b + i * 16 + (lane & 15)) * LDB + kb + ((lane >> 4) << 4));
    uint32_t bb[2][4];
#pragma unroll
    for (int p = 0; p < 2; ++p)
        ldm_x4(bb[p], sb + (uint32_t)(n0b + p * 16 + ((lane >> 4) << 3) + (lane & 7)) * LDB
                      + kb + (((lane >> 3) & 1) << 4));
#pragma unroll
    for (int i = 0; i < 2; ++i)
#pragma unroll
        for (int j = 0; j < 4; ++j)
            mma_f16_f32(acc[i][j], a[i], bb[j >> 1][(j & 1) * 2], bb[j >> 1][(j & 1) * 2 + 1]);
}

// ---- 32x64 warp-tile step, f16 acc (qk) ----
template <int LDB>
__device__ __forceinline__ void mma_step_h(uint32_t sa, uint32_t sb, int kb,
                                           int m0b, int n0b, int lane,
                                           uint32_t (&acc)[2][8][2])
{
    uint32_t a[2][4];
#pragma unroll
    for (int i = 0; i < 2; ++i)
        ldm_x4(a[i], sa + (uint32_t)(m0b + i * 16 + (lane & 15)) * LDB + kb + ((lane >> 4) << 4));
    uint32_t bb[4][4];
#pragma unroll
    for (int p = 0; p < 4; ++p)
        ldm_x4(bb[p], sb + (uint32_t)(n0b + p * 16 + ((lane >> 4) << 3) + (lane & 7)) * LDB
                      + kb + (((lane >> 3) & 1) << 4));
#pragma unroll
    for (int i = 0; i < 2; ++i)
#pragma unroll
        for (int j = 0; j < 8; ++j)
            mma_f16_f16(acc[i][j], a[i], bb[j >> 1][(j & 1) * 2], bb[j >> 1][(j & 1) * 2 + 1]);
}

// strides
constexpr int LD1 = 528;
constexpr int PROJ_AB = 64 * LD1;    // 33792
constexpr int DSP = 192 * LD1;       // 101376
constexpr int LD2 = 144;
constexpr int STG = 128 * LD2;       // 18432
constexpr int DS3 = 6 * STG;         // 110592
constexpr int PV_BSTG  = 256 * LD2;  // 36864
constexpr int PV_STAGE = STG + PV_BSTG;  // 55296
constexpr int DS4 = 4 * PV_STAGE;    // 221184
constexpr int OS_B = 128 * 528;      // 67584: O tile in smem (128 x 264 f16)

// ======================= K1: projections — 64x128 tile, 2 CTAs/SM =======================
__global__ __launch_bounds__(256, 2) void proj_mma_kernel(
    const float* __restrict__ q, const float* __restrict__ k, const float* __restrict__ v,
    const float* __restrict__ Wq, const float* __restrict__ bq,
    const float* __restrict__ Wk, const float* __restrict__ bk,
    const float* __restrict__ Wv, const float* __restrict__ bv)
{
    extern __shared__ __align__(16) char sm[];
    const uint32_t base = smem_u32(sm);
    const int tid = threadIdx.x, lane = tid & 31, wid = tid >> 5;
    const int row0 = blockIdx.y * 64, col0 = blockIdx.x * 128;
    const int m0b = (wid & 1) * 32, n0b = (wid >> 1) * 32;
    const int zz = blockIdx.z;

    const float *X, *W, *bias;
    if (zz == 0)      { X = q; W = Wq; bias = bq; }
    else if (zz == 1) { X = k; W = Wk; bias = bk; }
    else              { X = v; W = Wv; bias = bv; }

#pragma unroll
    for (int j = 0; j < 8; ++j) {
        int idx = tid + 256 * j;
        int r = idx >> 5, s = idx & 31;
        const float* xa = X + (size_t)(row0 + r) * CH + s * 8;
        float4 x0 = *(const float4*)xa, x1 = *(const float4*)(xa + 4);
        uint4 av = make_uint4(pack_h2(x0.x, x0.y), pack_h2(x0.z, x0.w),
                              pack_h2(x1.x, x1.y), pack_h2(x1.z, x1.w));
        *(uint4*)(sm + (size_t)r * LD1 + s * 16) = av;
    }
#pragma unroll
    for (int j = 0; j < 16; ++j) {
        int idx = tid + 256 * j;
        int r = idx >> 5, s = idx & 31;
        const float* wa = W + (size_t)(col0 + r) * CH + s * 8;
        float4 w0 = *(const float4*)wa, w1 = *(const float4*)(wa + 4);
        uint4 bv2 = make_uint4(pack_h2(w0.x, w0.y), pack_h2(w0.z, w0.w),
                               pack_h2(w1.x, w1.y), pack_h2(w1.z, w1.w));
        *(uint4*)(sm + PROJ_AB + (size_t)r * LD1 + s * 16) = bv2;
    }
    __syncthreads();

    float acc[2][4][4];
#pragma unroll
    for (int i = 0; i < 2; ++i)
#pragma unroll
        for (int j = 0; j < 4; ++j)
#pragma unroll
            for (int t = 0; t < 4; ++t) acc[i][j][t] = 0.f;

#pragma unroll
    for (int ks = 0; ks < 16; ++ks)
        mma_step32<LD1>(base, base + PROJ_AB, ks * 32, m0b, n0b, lane, acc);

    if (zz < 2) {
        __half* Y = (zz == 0) ? g_qh : g_kh;
#pragma unroll
        for (int i = 0; i < 2; ++i) {
            const int r = row0 + m0b + i * 16 + (lane >> 2);
#pragma unroll
            for (int j = 0; j < 4; ++j) {
                const int c = col0 + n0b + j * 8 + (lane & 3) * 2;
                float2 bv2 = *(const float2*)(bias + c);
                *(uint32_t*)(Y + (size_t)r * CH + c) =
                    pack_h2(acc[i][j][0] + bv2.x, acc[i][j][1] + bv2.y);
                *(uint32_t*)(Y + (size_t)(r + 8) * CH + c) =
                    pack_h2(acc[i][j][2] + bv2.x, acc[i][j][3] + bv2.y);
            }
        }
    } else {
        __syncthreads();
        __half* Cs = (__half*)sm;   // [64][136]
#pragma unroll
        for (int i = 0; i < 2; ++i) {
            const int rl = m0b + i * 16 + (lane >> 2);
#pragma unroll
            for (int j = 0; j < 4; ++j) {
                const int c = n0b + j * 8 + (lane & 3) * 2;
                float2 bv2 = *(const float2*)(bias + col0 + c);
                *(uint32_t*)(Cs + (size_t)rl * 136 + c) =
                    pack_h2(acc[i][j][0] + bv2.x, acc[i][j][1] + bv2.y);
                *(uint32_t*)(Cs + (size_t)(rl + 8) * 136 + c) =
                    pack_h2(acc[i][j][2] + bv2.x, acc[i][j][3] + bv2.y);
            }
        }
        __syncthreads();
        const int b = row0 >> 12;
        const int m0 = row0 & (SEQ - 1);
        __half* dst = g_vt + ((size_t)b * CH + col0) * SEQ + m0;
#pragma unroll
        for (int j = 0; j < 4; ++j) {
            int idx = tid + 256 * j;
            int c = idx >> 3, mu = idx & 7;
            __half tmp[8];
#pragma unroll
            for (int t = 0; t < 8; ++t) tmp[t] = Cs[(size_t)(mu * 8 + t) * 136 + c];
            *(uint4*)(dst + (size_t)c * SEQ + mu * 8) = *(uint4*)tmp;
        }
    }
}

// ======================= K2: S = q k^T (f16 acc, 3-stage) =======================
__global__ __launch_bounds__(256, 2) void qk_mma_kernel()
{
    extern __shared__ __align__(16) char sm[];
    const uint32_t base = smem_u32(sm);
    const int tid = threadIdx.x, lane = tid & 31, wid = tid >> 5;
    const int b = blockIdx.z, row0 = blockIdx.y * 128, col0 = blockIdx.x * 128;
    const int m0b = (wid & 3) * 32, n0b = (wid >> 2) * 64;

    const __half* A = g_qh + ((size_t)b * SEQ + row0) * CH;
    const __half* B = g_kh + ((size_t)b * SEQ + col0) * CH;

    uint32_t acc[2][8][2];
#pragma unroll
    for (int i = 0; i < 2; ++i)
#pragma unroll
        for (int j = 0; j < 8; ++j) { acc[i][j][0] = 0u; acc[i][j][1] = 0u; }

    auto issue = [&](int i) {
        const int k0 = i * 64;
        const uint32_t so = (uint32_t)(i % 3) * (2 * STG);
#pragma unroll
        for (int j = 0; j < 4; ++j) {
            int idx = tid + 256 * j;
            int r = idx >> 3, s = idx & 7;
            CP_ASYNC16(base + so + (uint32_t)r * LD2 + s * 16,
                       A + (size_t)r * CH + (k0 + s * 8));
            CP_ASYNC16(base + so + STG + (uint32_t)r * LD2 + s * 16,
                       B + (size_t)r * CH + (k0 + s * 8));
        }
        CP_COMMIT();
    };

    issue(0); issue(1);
    for (int i = 0; i < 4; ++i) {
        if (i + 1 < 4) { CP_WAIT(1); } else { CP_WAIT(0); }
        __syncthreads();
        if (i + 2 < 4) issue(i + 2);
        const uint32_t so = (uint32_t)(i % 3) * (2 * STG);
#pragma unroll
        for (int ks = 0; ks < 4; ++ks)
            mma_step_h<LD2>(base + so, base + so + STG, ks * 32, m0b, n0b, lane, acc);
    }

    __syncthreads();
    __half* Cs = (__half*)sm;
#pragma unroll
    for (int i = 0; i < 2; ++i) {
        const int r = m0b + i * 16 + (lane >> 2);
#pragma unroll
        for (int j = 0; j < 8; ++j) {
            const int c = n0b + j * 8 + (lane & 3) * 2;
            *(uint32_t*)(Cs + (size_t)r * 136 + c)       = acc[i][j][0];
            *(uint32_t*)(Cs + (size_t)(r + 8) * 136 + c) = acc[i][j][1];
        }
    }
    __syncthreads();
    __half* S = g_Sh + (size_t)b * SEQ * SEQ;
#pragma unroll
    for (int j = 0; j < 8; ++j) {
        int idx = tid + 256 * j;
        int r = idx >> 4, s = idx & 15;
        *(uint4*)(S + (size_t)(row0 + r) * SEQ + col0 + s * 8) =
            *(const uint4*)(Cs + (size_t)r * 136 + s * 8);
    }
}

// ======================= K3: stats + exp + Z per row (64 thr, 8x uint4) ===================
__global__ __launch_bounds__(64) void expz_kernel()
{
    const int row = blockIdx.x, tid = threadIdx.x;
    const int wid = tid >> 5, lane = tid & 31;
    uint4* srow = (uint4*)(g_Sh + (size_t)row * SEQ);
    uint4 d[8];
#pragma unroll
    for (int t = 0; t < 8; ++t) d[t] = srow[tid + 64 * t];
    float f[64];
#pragma unroll
    for (int t = 0; t < 8; ++t) {
        const uint32_t* u = (const uint32_t*)&d[t];
#pragma unroll
        for (int i = 0; i < 4; ++i) {
            float2 a = __half22float2(*(__half2*)&u[i]);
            f[t * 8 + 2 * i] = a.x; f[t * 8 + 2 * i + 1] = a.y;
        }
    }
    float sum = 0.f, ss = 0.f;
#pragma unroll
    for (int i = 0; i < 64; ++i) { sum += f[i]; ss = fmaf(f[i], f[i], ss); }
#pragma unroll
    for (int o = 16; o > 0; o >>= 1) {
        sum += __shfl_xor_sync(~0u, sum, o);
        ss  += __shfl_xor_sync(~0u, ss, o);
    }
    __shared__ float sA[2], sB[2];
    if (lane == 0) { sA[wid] = sum; sB[wid] = ss; }
    __syncthreads();
    float s  = sA[0] + sA[1];
    float qq = sB[0] + sB[1];
    float mu  = s * (1.f / SEQ);
    float var = qq * (1.f / SEQ) - mu * mu;
    float c   = rsqrtf(var + 1e-5f) * 0.0625f;
    float mc  = mu * c;

    float z = 0.f;
#pragma unroll
    for (int i = 0; i < 64; ++i) {
        float e = __expf(fmaf(f[i], c, -mc));
        f[i] = e; z += e;
    }
#pragma unroll
    for (int o = 16; o > 0; o >>= 1) z += __shfl_xor_sync(~0u, z, o);
    __syncthreads();
    if (lane == 0) sA[wid] = z;
#pragma unroll
    for (int t = 0; t < 8; ++t) {
        uint32_t* u = (uint32_t*)&d[t];
#pragma unroll
        for (int i = 0; i < 4; ++i)
            u[i] = pack_h2(f[t * 8 + 2 * i], f[t * 8 + 2 * i + 1]);
        srow[tid + 64 * t] = d[t];
    }
    __syncthreads();
    if (tid == 0)
        g_invZ[row] = 1.f / (sA[0] + sA[1]);
}

// ======================= K4: fused O = (P V)*invZ  ->  out = (query+O) Wm^T + bm =========
__global__ __launch_bounds__(512, 1) void pvf_mma_kernel(
    const float* __restrict__ query, const float* __restrict__ Wm,
    const float* __restrict__ bm, float* __restrict__ out)
{
    extern __shared__ __align__(16) char sm[];
    const uint32_t base = smem_u32(sm);
    const int tid = threadIdx.x, lane = tid & 31, wid = tid >> 5;
    const int b = blockIdx.z, row0 = blockIdx.x * 128;
    const int m0b = (wid & 3) * 32, n0b = (wid >> 2) * 64;

    const __half* P  = g_Sh + (size_t)b * SEQ * SEQ + (size_t)row0 * SEQ;
    const __half* Vt = g_vt + (size_t)b * CH * SEQ;

    float acc[2][8][4];
#pragma unroll
    for (int i = 0; i < 2; ++i)
#pragma unroll
        for (int j = 0; j < 8; ++j)
#pragma unroll
            for (int t = 0; t < 4; ++t) acc[i][j][t] = 0.f;

    auto issue = [&](int i) {
        const int k0 = i * 64;
        const uint32_t so = (uint32_t)(i & 3) * PV_STAGE;
#pragma unroll
        for (int j = 0; j < 2; ++j) {
            int idx = tid + 512 * j;
            int r = idx >> 3, s = idx & 7;
            CP_ASYNC16(base + so + (uint32_t)r * LD2 + s * 16,
                       P + (size_t)r * SEQ + (k0 + s * 8));
        }
#pragma unroll
        for (int j = 0; j < 4; ++j) {
            int idx = tid + 512 * j;
            int r = idx >> 3, s = idx & 7;
            CP_ASYNC16(base + so + STG + (uint32_t)r * LD2 + s * 16,
                       Vt + (size_t)r * SEQ + (k0 + s * 8));
        }
        CP_COMMIT();
    };

    issue(0); issue(1); issue(2); issue(3);
    for (int p = 0; p < 32; ++p) {
        const int i0 = 2 * p;
        if (p > 0) {
            __syncthreads();
            if (i0 + 2 < 64) issue(i0 + 2);
            if (i0 + 3 < 64) issue(i0 + 3);
        }
        if (i0 + 3 < 64) { CP_WAIT(2); } else { CP_WAIT(0); }
        if (p == 0) __syncthreads();
        const uint32_t so0 = (uint32_t)(i0 & 3) * PV_STAGE;
        const uint32_t so1 = (uint32_t)((i0 + 1) & 3) * PV_STAGE;
#pragma unroll
        for (int ks = 0; ks < 4; ++ks)
            mma_step<LD2>(base + so0, base + so0 + STG, ks * 32, m0b, n0b, lane, acc);
#pragma unroll
        for (int ks = 0; ks < 4; ++ks)
            mma_step<LD2>(base + so1, base + so1 + STG, ks * 32, m0b, n0b, lane, acc);
    }

    // ---- O -> smem (f16, stride 264 elems = 528 B) ----
    __syncthreads();                 // all warps done reading stage buffers
    __half* Os = (__half*)sm;
#pragma unroll
    for (int i = 0; i < 2; ++i) {
        const int rl = m0b + i * 16 + (lane >> 2);
        const float izA = g_invZ[b * SEQ + row0 + rl];
        const float izB = g_invZ[b * SEQ + row0 + rl + 8];
#pragma unroll
        for (int j = 0; j < 8; ++j) {
            const int c = n0b + j * 8 + (lane & 3) * 2;
            *(uint32_t*)(Os + (size_t)rl * 264 + c) =
                pack_h2(acc[i][j][0] * izA, acc[i][j][1] * izA);
            *(uint32_t*)(Os + (size_t)(rl + 8) * 264 + c) =
                pack_h2(acc[i][j][2] * izB, acc[i][j][3] * izB);
        }
    }

    // ---- final GEMM: out[128 x 256] = (query + O) @ Wm^T + bm (bf16x3) ----
    const uint32_t sAhi = base + OS_B;
    const uint32_t sAlo = sAhi + STG;
    const uint32_t sBhi = sAlo + STG;
    const uint32_t sBlo = sBhi + PV_BSTG;

#pragma unroll
    for (int i = 0; i < 2; ++i)
#pragma unroll
        for (int j = 0; j < 8; ++j)
#pragma unroll
            for (int t = 0; t < 4; ++t) acc[i][j][t] = 0.f;

    for (int ch = 0; ch < 4; ++ch) {
        const int k0 = ch * 64;
        __syncthreads();
        // stage A = query + O (128 rows x 64 cols), split hi/lo
#pragma unroll
        for (int j = 0; j < 2; ++j) {
            int idx = tid + 512 * j;
            int r = idx >> 3, s = idx & 7;
            const float* qa = query + (size_t)(b * SEQ + row0 + r) * CH + k0 + s * 8;
            float av[8];
            *(float4*)&av[0] = *(const float4*)qa;
            *(float4*)&av[4] = *(const float4*)(qa + 4);
            uint4 ov = *(const uint4*)(sm + (size_t)r * 528 + (k0 + s * 8) * 2);
            const uint32_t* ou = (const uint32_t*)&ov;
            uint4 hi, lo;
            uint32_t* hp = (uint32_t*)&hi; uint32_t* lp = (uint32_t*)&lo;
#pragma unroll
            for (int t = 0; t < 4; ++t) {
                float2 o2 = __half22float2(*(__half2*)&ou[t]);
                float a0 = av[2 * t] + o2.x, a1 = av[2 * t + 1] + o2.y;
                __nv_bfloat16 h0 = __float2bfloat16_rn(a0), h1 = __float2bfloat16_rn(a1);
                float l0 = a0 - __bfloat162float(h0), l1 = a1 - __bfloat162float(h1);
                hp[t] = ((uint32_t)*(uint16_t*)&h1 << 16) | *(uint16_t*)&h0;
                lp[t] = pack_bf2(l0, l1);
            }
            const uint32_t doff = (uint32_t)r * LD2 + s * 16;
            *(uint4*)(sAhi - base + sm + doff) = hi;   // sAhi is byte addr; use pointer form
            *(uint4*)(sAlo - base + sm + doff) = lo;
        }
        // stage B = Wm (256 rows x 64 cols), split hi/lo
#pragma unroll
        for (int j = 0; j < 4; ++j) {
            int idx = tid + 512 * j;
            int r = idx >> 3, s = idx & 7;
            const float* wa = Wm + (size_t)r * CH + k0 + s * 8;
            float wv[8];
            *(float4*)&wv[0] = *(const float4*)wa;
            *(float4*)&wv[4] = *(const float4*)(wa + 4);
            uint4 hi, lo;
            uint32_t* hp = (uint32_t*)&hi; uint32_t* lp = (uint32_t*)&lo;
#pragma unroll
            for (int t = 0; t < 4; ++t) {
                float a0 = wv[2 * t], a1 = wv[2 * t + 1];
                __nv_bfloat16 h0 = __float2bfloat16_rn(a0), h1 = __float2bfloat16_rn(a1);
                float l0 = a0 - __bfloat162float(h0), l1 = a1 - __bfloat162float(h1);
                hp[t] = ((uint32_t)*(uint16_t*)&h1 << 16) | *(uint16_t*)&h0;
                lp[t] = pack_bf2(l0, l1);
            }
            const uint32_t doff = (uint32_t)r * LD2 + s * 16;
            *(uint4*)(sBhi - base + sm + doff) = hi;
            *(uint4*)(sBlo - base + sm + doff) = lo;
        }
        __syncthreads();

#pragma unroll
        for (int ks = 0; ks < 4; ++ks) {
            const int kb = ks * 32;
            uint32_t ah[2][4], al[2][4];
#pragma unroll
            for (int i = 0; i < 2; ++i) {
                const uint32_t ao = (uint32_t)(m0b + i * 16 + (lane & 15)) * LD2 + kb + ((lane >> 4) << 4);
                ldm_x4(ah[i], sAhi + ao);
                ldm_x4(al[i], sAlo + ao);
            }
            uint32_t bh[4][4], bl[4][4];
#pragma unroll
            for (int p = 0; p < 4; ++p) {
                const uint32_t bo = (uint32_t)(n0b + p * 16 + ((lane >> 4) << 3) + (lane & 7)) * LD2
                                    + kb + (((lane >> 3) & 1) << 4);
                ldm_x4(bh[p], sBhi + bo);
                ldm_x4(bl[p], sBlo + bo);
            }
#pragma unroll
            for (int i = 0; i < 2; ++i)
#pragma unroll
                for (int j = 0; j < 8; ++j) {
                    uint32_t bh0 = bh[j >> 1][(j & 1) * 2], bh1 = bh[j >> 1][(j & 1) * 2 + 1];
                    uint32_t bl0 = bl[j >> 1][(j & 1) * 2], bl1 = bl[j >> 1][(j & 1) * 2 + 1];
                    mma_bf16(acc[i][j], ah[i], bh0, bh1);
                    mma_bf16(acc[i][j], ah[i], bl0, bl1);
                    mma_bf16(acc[i][j], al[i], bh0, bh1);
                }
        }
    }

#pragma unroll
    for (int i = 0; i < 2; ++i) {
        const int r = b * SEQ + row0 + m0b + i * 16 + (lane >> 2);
#pragma unroll
        for (int j = 0; j < 8; ++j) {
            const int c = n0b + j * 8 + (lane & 3) * 2;
            float2 bv2 = *(const float2*)(bm + c);
            *(float2*)(out + (size_t)r * CH + c) =
                make_float2(acc[i][j][0] + bv2.x, acc[i][j][1] + bv2.y);
            *(float2*)(out + (size_t)(r + 8) * CH + c) =
                make_float2(acc[i][j][2] + bv2.x, acc[i][j][3] + bv2.y);
        }
    }
}

extern "C" void kernel_launch(void* const* d_in, const int* in_sizes, int n_in,
                              void* d_out, int out_size)
{
    const float* query = (const float*)d_in[0];
    const float* key   = (const float*)d_in[1];
    const float* value = (const float*)d_in[2];
    const float* Wq    = (const float*)d_in[3];
    const float* bq    = (const float*)d_in[4];
    const float* Wk    = (const float*)d_in[5];
    const float* bk    = (const float*)d_in[6];
    const float* Wv    = (const float*)d_in[7];
    const float* bv    = (const float*)d_in[8];
    const float* Wm    = (const float*)d_in[9];
    const float* bm    = (const float*)d_in[10];
    float* out = (float*)d_out;

    cudaFuncSetAttribute(proj_mma_kernel, cudaFuncAttributeMaxDynamicSharedMemorySize, DSP);
    cudaFuncSetAttribute(qk_mma_kernel,   cudaFuncAttributeMaxDynamicSharedMemorySize, DS3);
    cudaFuncSetAttribute(pvf_mma_kernel,  cudaFuncAttributeMaxDynamicSharedMemorySize, DS4);

    proj_mma_kernel<<<dim3(2, 256, 3), 256, DSP>>>(query, key, value, Wq, bq, Wk, bk, Wv, bv);
    qk_mma_kernel<<<dim3(32, 32, 4), 256, DS3>>>();
    expz_kernel<<<ROWS, 64>>>();
    pvf_mma_kernel<<<dim3(32, 1, 4), 512, DS4>>>(query, Wm, bm, out);
}